// round 3
// baseline (speedup 1.0000x reference)
#include <cuda_runtime.h>
#include <math_constants.h>

// Problem constants (fixed by the dataset reference)
#define BATCH   8
#define NPTS    16384
#define MPTS    4096
#define CS      256     // sampled_features channels
#define CF      128     // features channels
#define COUT    (CS + CF)

#define THREADS 256
#define QPT     2                   // queries per thread
#define TILE    (THREADS * QPT)     // 512 queries per block
#define CHUNK   2048                // candidates per smem chunk (32KB of float4)
#define NCHUNK  (MPTS / CHUNK)

__global__ __launch_bounds__(THREADS)
void upsample_knn_interp_kernel(
    const float* __restrict__ xyz,      // [B,N,3]
    const float* __restrict__ sxyz,     // [B,M,3]
    const float* __restrict__ feat,     // [B,N,CF]
    const float* __restrict__ sfeat,    // [B,M,CS]
    float* __restrict__ out)            // [B,N,CS+CF]
{
    // 32KB buffer: candidate table (float4 per candidate) during KNN,
    // overlaid with per-query (weights, indices) for the epilogue.
    __shared__ __align__(16) float smem[CHUNK * 4];
    float* sw = smem;                      // [TILE*3] weights
    int*   si = (int*)(smem + TILE * 3);   // [TILE*3] indices

    const int b     = blockIdx.y;
    const int tile0 = blockIdx.x * TILE;
    const int tid   = threadIdx.x;

    const float* xb = xyz  + (size_t)b * NPTS * 3;
    const float* yb = sxyz + (size_t)b * MPTS * 3;

    // Per-thread query state
    float nx0[QPT], nx1[QPT], nx2[QPT], xn2[QPT];
    float bs0[QPT], bs1[QPT], bs2[QPT];
    int   bi0[QPT], bi1[QPT], bi2[QPT];

    #pragma unroll
    for (int q = 0; q < QPT; q++) {
        int n = tile0 + tid + q * THREADS;
        float x0 = xb[n * 3 + 0];
        float x1 = xb[n * 3 + 1];
        float x2 = xb[n * 3 + 2];
        nx0[q] = -x0; nx1[q] = -x1; nx2[q] = -x2;
        xn2[q] = x0 * x0 + x1 * x1 + x2 * x2;
        bs0[q] = CUDART_INF_F; bs1[q] = CUDART_INF_F; bs2[q] = CUDART_INF_F;
        bi0[q] = 0; bi1[q] = 0; bi2[q] = 0;
    }

    // ---------------- KNN scan over M candidates, chunked through smem ------
    for (int ch = 0; ch < NCHUNK; ch++) {
        __syncthreads();   // previous chunk fully consumed before overwrite
        const int base = ch * CHUNK;
        for (int j = tid; j < CHUNK; j += THREADS) {
            const float y0 = yb[(base + j) * 3 + 0];
            const float y1 = yb[(base + j) * 3 + 1];
            const float y2 = yb[(base + j) * 3 + 2];
            const float h  = 0.5f * (y0 * y0 + y1 * y1 + y2 * y2);
            ((float4*)smem)[j] = make_float4(y0, y1, y2, h);
        }
        __syncthreads();

        #pragma unroll 4
        for (int j = 0; j < CHUNK; j++) {
            const float4 y = ((const float4*)smem)[j];   // broadcast LDS.128
            #pragma unroll
            for (int q = 0; q < QPT; q++) {
                // s = 0.5|y|^2 - x.y   (monotonic with squared distance)
                float s = fmaf(y.x, nx0[q], fmaf(y.y, nx1[q], fmaf(y.z, nx2[q], y.w)));
                if (s < bs2[q]) {
                    const int jj = base + j;
                    if (s < bs1[q]) {
                        bs2[q] = bs1[q]; bi2[q] = bi1[q];
                        if (s < bs0[q]) {
                            bs1[q] = bs0[q]; bi1[q] = bi0[q];
                            bs0[q] = s;      bi0[q] = jj;
                        } else {
                            bs1[q] = s;      bi1[q] = jj;
                        }
                    } else {
                        bs2[q] = s; bi2[q] = jj;
                    }
                }
            }
        }
    }

    __syncthreads();   // scan done everywhere; safe to overlay smem

    // ---------------- weights -> smem ---------------------------------------
    #pragma unroll
    for (int q = 0; q < QPT; q++) {
        const int lq = tid + q * THREADS;
        float w0, w1, w2;
        {
            float d0 = fmaxf(fmaf(2.0f, bs0[q], xn2[q]), 1e-10f);
            float d1 = fmaxf(fmaf(2.0f, bs1[q], xn2[q]), 1e-10f);
            float d2 = fmaxf(fmaf(2.0f, bs2[q], xn2[q]), 1e-10f);
            w0 = 1.0f / (d0 * d0 + 1e-7f);
            w1 = 1.0f / (d1 * d1 + 1e-7f);
            w2 = 1.0f / (d2 * d2 + 1e-7f);
        }
        const float inv = 1.0f / (w0 + w1 + w2 + 1e-10f);
        sw[lq * 3 + 0] = w0 * inv;
        sw[lq * 3 + 1] = w1 * inv;
        sw[lq * 3 + 2] = w2 * inv;
        si[lq * 3 + 0] = bi0[q];
        si[lq * 3 + 1] = bi1[q];
        si[lq * 3 + 2] = bi2[q];
    }
    __syncthreads();

    // ---------------- gather + interp + concat ------------------------------
    const float4* sfb = (const float4*)(sfeat + (size_t)b * MPTS * CS);
    const float4* fb  = (const float4*)(feat  + (size_t)b * NPTS * CF);
    float4*       ob  = (float4*)(out + (size_t)b * NPTS * COUT);

    const int warp = tid >> 5;
    const int lane = tid & 31;
    const int nwarp = THREADS / 32;

    for (int lq = warp; lq < TILE; lq += nwarp) {
        const int n = tile0 + lq;
        const float w0 = sw[lq * 3 + 0];
        const float w1 = sw[lq * 3 + 1];
        const float w2 = sw[lq * 3 + 2];
        const float4* r0 = sfb + (size_t)si[lq * 3 + 0] * (CS / 4);
        const float4* r1 = sfb + (size_t)si[lq * 3 + 1] * (CS / 4);
        const float4* r2 = sfb + (size_t)si[lq * 3 + 2] * (CS / 4);
        float4* o = ob + (size_t)n * (COUT / 4);

        #pragma unroll
        for (int c = lane; c < CS / 4; c += 32) {
            const float4 a = r0[c];
            const float4 d = r1[c];
            const float4 e = r2[c];
            float4 rv;
            rv.x = w0 * a.x + w1 * d.x + w2 * e.x;
            rv.y = w0 * a.y + w1 * d.y + w2 * e.y;
            rv.z = w0 * a.z + w1 * d.z + w2 * e.z;
            rv.w = w0 * a.w + w1 * d.w + w2 * e.w;
            o[c] = rv;
        }
        // concat features: 128 floats = 32 float4, exactly one per lane
        const float4* f = fb + (size_t)n * (CF / 4);
        o[CS / 4 + lane] = f[lane];
    }
}

extern "C" void kernel_launch(void* const* d_in, const int* in_sizes, int n_in,
                              void* d_out, int out_size)
{
    const float* xyz   = (const float*)d_in[0];
    const float* sxyz  = (const float*)d_in[1];
    const float* feat  = (const float*)d_in[2];
    const float* sfeat = (const float*)d_in[3];
    float* out = (float*)d_out;

    dim3 grid(NPTS / TILE, BATCH);   // 32 x 8 = 256 blocks
    upsample_knn_interp_kernel<<<grid, THREADS>>>(xyz, sxyz, feat, sfeat, out);
}

// round 4
// speedup vs baseline: 1.0032x; 1.0032x over previous
#include <cuda_runtime.h>
#include <math_constants.h>

// Problem constants (fixed by the dataset reference)
#define BATCH   8
#define NPTS    16384
#define MPTS    4096
#define CS      256
#define CF      128
#define COUT    (CS + CF)

#define THREADS 256
#define QPT     2
#define TILE    (THREADS * QPT)         // 512 queries / CTA (phase 1)
#define SPLITS  8
#define SLEN    (MPTS / SPLITS)         // 512 candidates per split (= reference BLOCK)

// Partial-result scratch: layout [j][split][b][n]  (j = rank 0..2)
// 3 * 8 * 8 * 16384 = 3.15M elements each -> 12.6 MB float + 12.6 MB int
__device__ float g_pd[3 * SPLITS * BATCH * NPTS];
__device__ int   g_pi[3 * SPLITS * BATCH * NPTS];

// ---------------------------------------------------------------------------
// Phase 1: per-split 3-NN scan. Grid (N/TILE, B, SPLITS), 256 thr, 8KB smem.
// ---------------------------------------------------------------------------
__global__ __launch_bounds__(THREADS)
void knn_partial_kernel(const float* __restrict__ xyz,
                        const float* __restrict__ sxyz)
{
    __shared__ __align__(16) float4 sc[SLEN];   // (y0,y1,y2, 0.5*|y|^2)

    const int b     = blockIdx.y;
    const int split = blockIdx.z;
    const int tile0 = blockIdx.x * TILE;
    const int tid   = threadIdx.x;
    const int cbase = split * SLEN;

    const float* xb = xyz  + (size_t)b * NPTS * 3;
    const float* yb = sxyz + ((size_t)b * MPTS + cbase) * 3;

    // stage candidate slice into smem
    for (int j = tid; j < SLEN; j += THREADS) {
        const float y0 = yb[j * 3 + 0];
        const float y1 = yb[j * 3 + 1];
        const float y2 = yb[j * 3 + 2];
        sc[j] = make_float4(y0, y1, y2, 0.5f * (y0 * y0 + y1 * y1 + y2 * y2));
    }

    float nx0[QPT], nx1[QPT], nx2[QPT], xn2[QPT];
    float bs0[QPT], bs1[QPT], bs2[QPT];
    int   bi0[QPT], bi1[QPT], bi2[QPT];

    #pragma unroll
    for (int q = 0; q < QPT; q++) {
        const int n = tile0 + tid + q * THREADS;
        const float x0 = xb[n * 3 + 0];
        const float x1 = xb[n * 3 + 1];
        const float x2 = xb[n * 3 + 2];
        nx0[q] = -x0; nx1[q] = -x1; nx2[q] = -x2;
        xn2[q] = x0 * x0 + x1 * x1 + x2 * x2;
        bs0[q] = CUDART_INF_F; bs1[q] = CUDART_INF_F; bs2[q] = CUDART_INF_F;
        bi0[q] = 0; bi1[q] = 0; bi2[q] = 0;
    }
    __syncthreads();

    #pragma unroll 4
    for (int j = 0; j < SLEN; j++) {
        const float4 y = sc[j];                 // broadcast LDS.128
        #pragma unroll
        for (int q = 0; q < QPT; q++) {
            // s = 0.5|y|^2 - x.y  (monotone in squared distance)
            const float s = fmaf(y.x, nx0[q], fmaf(y.y, nx1[q], fmaf(y.z, nx2[q], y.w)));
            if (s < bs2[q]) {                   // rare path
                if (s < bs1[q]) {
                    bs2[q] = bs1[q]; bi2[q] = bi1[q];
                    if (s < bs0[q]) {
                        bs1[q] = bs0[q]; bi1[q] = bi0[q];
                        bs0[q] = s;      bi0[q] = j;
                    } else {
                        bs1[q] = s;      bi1[q] = j;
                    }
                } else {
                    bs2[q] = s; bi2[q] = j;
                }
            }
        }
    }

    // write partials: d = 2s + |x|^2 (exact same value as fused round-3 math)
    const size_t sb = ((size_t)split * BATCH + b) * NPTS;
    const size_t jstride = (size_t)SPLITS * BATCH * NPTS;
    #pragma unroll
    for (int q = 0; q < QPT; q++) {
        const int n = tile0 + tid + q * THREADS;
        g_pd[0 * jstride + sb + n] = fmaf(2.0f, bs0[q], xn2[q]);
        g_pd[1 * jstride + sb + n] = fmaf(2.0f, bs1[q], xn2[q]);
        g_pd[2 * jstride + sb + n] = fmaf(2.0f, bs2[q], xn2[q]);
        g_pi[0 * jstride + sb + n] = cbase + bi0[q];
        g_pi[1 * jstride + sb + n] = cbase + bi1[q];
        g_pi[2 * jstride + sb + n] = cbase + bi2[q];
    }
}

// ---------------------------------------------------------------------------
// Phase 2: merge partials + interp + concat. Warp per query.
// Grid (N/8, B), 256 threads (8 warps).
// ---------------------------------------------------------------------------
__global__ __launch_bounds__(THREADS)
void merge_interp_kernel(const float* __restrict__ feat,
                         const float* __restrict__ sfeat,
                         float* __restrict__ out)
{
    const int b    = blockIdx.y;
    const int warp = threadIdx.x >> 5;
    const int lane = threadIdx.x & 31;
    const int n    = blockIdx.x * (THREADS / 32) + warp;

    // merge 8 splits x 3 ranks (redundant per lane; loads are warp-broadcast).
    // strict < keeps earliest (split, rank) on ties -> matches reference's
    // stable blockwise top_k merge.
    float bd0 = CUDART_INF_F, bd1 = CUDART_INF_F, bd2 = CUDART_INF_F;
    int   bi0 = 0, bi1 = 0, bi2 = 0;
    const size_t jstride = (size_t)SPLITS * BATCH * NPTS;

    #pragma unroll
    for (int sp = 0; sp < SPLITS; sp++) {
        const size_t sb = ((size_t)sp * BATCH + b) * NPTS + n;
        #pragma unroll
        for (int j = 0; j < 3; j++) {
            const float d = g_pd[(size_t)j * jstride + sb];
            const int   i = g_pi[(size_t)j * jstride + sb];
            if (d < bd2) {
                if (d < bd1) {
                    bd2 = bd1; bi2 = bi1;
                    if (d < bd0) { bd1 = bd0; bi1 = bi0; bd0 = d; bi0 = i; }
                    else         { bd1 = d;   bi1 = i; }
                } else { bd2 = d; bi2 = i; }
            }
        }
    }

    // inverse-distance weights (P=2)
    bd0 = fmaxf(bd0, 1e-10f);
    bd1 = fmaxf(bd1, 1e-10f);
    bd2 = fmaxf(bd2, 1e-10f);
    float w0 = 1.0f / (bd0 * bd0 + 1e-7f);
    float w1 = 1.0f / (bd1 * bd1 + 1e-7f);
    float w2 = 1.0f / (bd2 * bd2 + 1e-7f);
    const float inv = 1.0f / (w0 + w1 + w2 + 1e-10f);
    w0 *= inv; w1 *= inv; w2 *= inv;

    // gather + interpolate + concat
    const float4* sfb = (const float4*)(sfeat + (size_t)b * MPTS * CS);
    const float4* fb  = (const float4*)(feat  + (size_t)b * NPTS * CF);
    float4*       ob  = (float4*)(out + (size_t)b * NPTS * COUT);

    const float4* r0 = sfb + (size_t)bi0 * (CS / 4);
    const float4* r1 = sfb + (size_t)bi1 * (CS / 4);
    const float4* r2 = sfb + (size_t)bi2 * (CS / 4);
    float4* o = ob + (size_t)n * (COUT / 4);

    #pragma unroll
    for (int c = lane; c < CS / 4; c += 32) {
        const float4 a = r0[c];
        const float4 d = r1[c];
        const float4 e = r2[c];
        float4 rv;
        rv.x = w0 * a.x + w1 * d.x + w2 * e.x;
        rv.y = w0 * a.y + w1 * d.y + w2 * e.y;
        rv.z = w0 * a.z + w1 * d.z + w2 * e.z;
        rv.w = w0 * a.w + w1 * d.w + w2 * e.w;
        o[c] = rv;
    }
    const float4* f = fb + (size_t)n * (CF / 4);
    o[CS / 4 + lane] = f[lane];
}

extern "C" void kernel_launch(void* const* d_in, const int* in_sizes, int n_in,
                              void* d_out, int out_size)
{
    const float* xyz   = (const float*)d_in[0];
    const float* sxyz  = (const float*)d_in[1];
    const float* feat  = (const float*)d_in[2];
    const float* sfeat = (const float*)d_in[3];
    float* out = (float*)d_out;

    dim3 g1(NPTS / TILE, BATCH, SPLITS);     // 32 x 8 x 8 = 2048 CTAs
    knn_partial_kernel<<<g1, THREADS>>>(xyz, sxyz);

    dim3 g2(NPTS / (THREADS / 32), BATCH);   // 2048 x 8 CTAs
    merge_interp_kernel<<<g2, THREADS>>>(feat, sfeat, out);
}

// round 6
// speedup vs baseline: 1.0904x; 1.0869x over previous
#include <cuda_runtime.h>

// Problem constants (fixed by the dataset reference)
#define BATCH   8
#define NPTS    16384
#define MPTS    4096
#define CS      256
#define CF      128
#define COUT    (CS + CF)

#define SPLITS  8
#define SLEN    (MPTS / SPLITS)        // 512 candidates per split (9-bit local idx)

#define T1      256                    // phase-1 threads
#define QPT     4
#define TILE    (T1 * QPT)             // 1024 queries per phase-1 CTA

// Packed partials: key = (float_bits(d/2) & 0xFFFFFE00) | local_idx9
// 14 mantissa bits kept; exact re-scoring happens in phase 2.
// Layout [b][split][rank][n] -> coalesced stores/loads.
__device__ int g_pk[BATCH * SPLITS * 3 * NPTS];   // 12.6 MB

// ---------------------------------------------------------------------------
// Phase 1: branch-free per-split 3-NN. Grid (16, 8, 8), 256 thr, 8 KB smem.
// ---------------------------------------------------------------------------
__global__ __launch_bounds__(T1)
void knn_partial_kernel(const float* __restrict__ xyz,
                        const float* __restrict__ sxyz)
{
    __shared__ __align__(16) float4 sc[SLEN];     // (y0,y1,y2, 0.5*|y|^2)

    const int b     = blockIdx.y;
    const int sp    = blockIdx.z;
    const int tile0 = blockIdx.x * TILE;
    const int tid   = threadIdx.x;
    const int cbase = sp * SLEN;

    const float* xb = xyz  + (size_t)b * NPTS * 3;
    const float* yb = sxyz + ((size_t)b * MPTS + cbase) * 3;

    for (int j = tid; j < SLEN; j += T1) {
        const float y0 = yb[j * 3 + 0];
        const float y1 = yb[j * 3 + 1];
        const float y2 = yb[j * 3 + 2];
        sc[j] = make_float4(y0, y1, y2, 0.5f * (y0 * y0 + y1 * y1 + y2 * y2));
    }

    float nx[QPT], ny[QPT], nz[QPT], hx[QPT];
    int   k0[QPT], k1[QPT], k2[QPT];

    #pragma unroll
    for (int q = 0; q < QPT; q++) {
        const int n = tile0 + tid + q * T1;
        const float x0 = xb[n * 3 + 0];
        const float x1 = xb[n * 3 + 1];
        const float x2 = xb[n * 3 + 2];
        nx[q] = -x0; ny[q] = -x1; nz[q] = -x2;
        hx[q] = 0.5f * (x0 * x0 + x1 * x1 + x2 * x2);
        k0[q] = 0x7FFFFFFF; k1[q] = 0x7FFFFFFF; k2[q] = 0x7FFFFFFF;
    }
    __syncthreads();

    #pragma unroll 4
    for (int j = 0; j < SLEN; j++) {
        const float4 y = sc[j];           // broadcast LDS.128
        #pragma unroll
        for (int q = 0; q < QPT; q++) {
            // s = 0.5|x|^2 + 0.5|y|^2 - x.y = d/2 >= 0 (mod rounding)
            const float s = fmaf(y.x, nx[q],
                            fmaf(y.y, ny[q],
                            fmaf(y.z, nz[q], hx[q] + y.w)));
            // sortable key: 14 mantissa bits | 9-bit local idx (tie -> lower idx)
            const int key = (__float_as_int(s) & (int)0xFFFFFE00) | j;
            // branch-free sorted insert (k0 <= k1 <= k2): 5 IMNMX
            const int M0 = max(k0[q], key);  k0[q] = min(k0[q], key);
            const int M1 = max(k1[q], M0);   k1[q] = min(k1[q], M0);
            k2[q] = min(k2[q], M1);
        }
    }

    const size_t base = ((size_t)(b * SPLITS + sp) * 3) * NPTS;
    #pragma unroll
    for (int q = 0; q < QPT; q++) {
        const int n = tile0 + tid + q * T1;
        g_pk[base + 0 * NPTS + n] = k0[q];
        g_pk[base + 1 * NPTS + n] = k1[q];
        g_pk[base + 2 * NPTS + n] = k2[q];
    }
}

// ---------------------------------------------------------------------------
// Phase 2: exact re-score of 24 partials, warp top-3, interp + concat.
// Grid (2048, 8), 256 threads (warp per query).
// ---------------------------------------------------------------------------
__device__ __forceinline__ unsigned long long warp_min_u64(unsigned long long v) {
    #pragma unroll
    for (int off = 16; off > 0; off >>= 1) {
        const unsigned long long o = __shfl_xor_sync(0xFFFFFFFFu, v, off);
        v = (o < v) ? o : v;
    }
    return v;
}

__global__ __launch_bounds__(256)
void merge_interp_kernel(const float* __restrict__ xyz,
                         const float* __restrict__ sxyz,
                         const float* __restrict__ feat,
                         const float* __restrict__ sfeat,
                         float* __restrict__ out)
{
    const int b    = blockIdx.y;
    const int warp = threadIdx.x >> 5;
    const int lane = threadIdx.x & 31;
    const int n    = blockIdx.x * 8 + warp;

    const float* xq = xyz  + ((size_t)b * NPTS + n) * 3;
    const float* yB = sxyz + (size_t)b * MPTS * 3;
    const float x0 = __ldg(xq + 0), x1 = __ldg(xq + 1), x2 = __ldg(xq + 2);

    // lanes 0..23: one (split,rank) partial each; exact distance re-score
    unsigned long long pack = ~0ull;
    if (lane < SPLITS * 3) {
        const int key = g_pk[((size_t)b * SPLITS * 3 + lane) * NPTS + n];
        const int sp  = lane / 3;                         // lane -> split
        const int gi  = sp * SLEN + (key & (SLEN - 1));   // global candidate idx
        const float e0 = x0 - __ldg(yB + gi * 3 + 0);
        const float e1 = x1 - __ldg(yB + gi * 3 + 1);
        const float e2 = x2 - __ldg(yB + gi * 3 + 2);
        const float dd = fmaf(e0, e0, fmaf(e1, e1, e2 * e2));
        // exact key: (d_bits << 32) | global_idx ; min => closest, tie -> lower idx
        pack = ((unsigned long long)(unsigned)__float_as_int(dd) << 32) |
               (unsigned)gi;
    }

    const unsigned long long m0 = warp_min_u64(pack);
    pack = (pack == m0) ? ~0ull : pack;
    const unsigned long long m1 = warp_min_u64(pack);
    pack = (pack == m1) ? ~0ull : pack;
    const unsigned long long m2 = warp_min_u64(pack);

    const int i0 = (int)(unsigned)m0 & (MPTS - 1);
    const int i1 = (int)(unsigned)m1 & (MPTS - 1);
    const int i2 = (int)(unsigned)m2 & (MPTS - 1);
    float d0 = __int_as_float((int)(m0 >> 32));
    float d1 = __int_as_float((int)(m1 >> 32));
    float d2 = __int_as_float((int)(m2 >> 32));

    d0 = fmaxf(d0, 1e-10f);
    d1 = fmaxf(d1, 1e-10f);
    d2 = fmaxf(d2, 1e-10f);
    float w0 = 1.0f / (d0 * d0 + 1e-7f);
    float w1 = 1.0f / (d1 * d1 + 1e-7f);
    float w2 = 1.0f / (d2 * d2 + 1e-7f);
    const float inv = 1.0f / (w0 + w1 + w2 + 1e-10f);
    w0 *= inv; w1 *= inv; w2 *= inv;

    // gather + interpolate + concat
    const float4* sfb = (const float4*)(sfeat + (size_t)b * MPTS * CS);
    const float4* fb  = (const float4*)(feat  + (size_t)b * NPTS * CF);
    float4*       ob  = (float4*)(out + (size_t)b * NPTS * COUT);

    const float4* r0 = sfb + (size_t)i0 * (CS / 4);
    const float4* r1 = sfb + (size_t)i1 * (CS / 4);
    const float4* r2 = sfb + (size_t)i2 * (CS / 4);
    float4* o = ob + (size_t)n * (COUT / 4);

    #pragma unroll
    for (int c = lane; c < CS / 4; c += 32) {
        const float4 a = r0[c];
        const float4 d = r1[c];
        const float4 e = r2[c];
        float4 rv;
        rv.x = w0 * a.x + w1 * d.x + w2 * e.x;
        rv.y = w0 * a.y + w1 * d.y + w2 * e.y;
        rv.z = w0 * a.z + w1 * d.z + w2 * e.z;
        rv.w = w0 * a.w + w1 * d.w + w2 * e.w;
        o[c] = rv;
    }
    const float4* f = fb + (size_t)n * (CF / 4);
    o[CS / 4 + lane] = f[lane];
}

extern "C" void kernel_launch(void* const* d_in, const int* in_sizes, int n_in,
                              void* d_out, int out_size)
{
    const float* xyz   = (const float*)d_in[0];
    const float* sxyz  = (const float*)d_in[1];
    const float* feat  = (const float*)d_in[2];
    const float* sfeat = (const float*)d_in[3];
    float* out = (float*)d_out;

    dim3 g1(NPTS / TILE, BATCH, SPLITS);    // 16 x 8 x 8 = 1024 CTAs
    knn_partial_kernel<<<g1, T1>>>(xyz, sxyz);

    dim3 g2(NPTS / 8, BATCH);               // 2048 x 8, warp per query
    merge_interp_kernel<<<g2, 256>>>(xyz, sxyz, feat, sfeat, out);
}

// round 8
// speedup vs baseline: 1.1058x; 1.0141x over previous
#include <cuda_runtime.h>
#include <math_constants.h>

// Problem constants (fixed by the dataset reference)
#define BATCH   8
#define NPTS    16384
#define MPTS    4096
#define CS      256
#define CF      128
#define COUT    (CS + CF)

#define SPLITS  8
#define SLEN    (MPTS / SPLITS)        // 512 candidates per split (9-bit local idx)

#define T1      128                    // phase-1 threads
#define QPT     2
#define TILE    (T1 * QPT)             // 256 queries per item
#define NTILES  (NPTS / TILE)          // 64
#define ITEMS   (NTILES * BATCH * SPLITS)  // 4096
#define G1      592                    // 148 SMs x 4 CTAs: one resident wave

// Exact partials: {d_bits, global_idx} per (b, slot=sp*3+rank, n). 25 MB.
__device__ int2 g_pp[BATCH * SPLITS * 3 * NPTS];

// ---------------------------------------------------------------------------
// Phase 1: persistent branch-free per-split 3-NN. Grid 592 x 128 thr, 8KB smem.
// ---------------------------------------------------------------------------
__global__ __launch_bounds__(T1, 4)
void knn_partial_kernel(const float* __restrict__ xyz,
                        const float* __restrict__ sxyz)
{
    __shared__ __align__(16) float4 sc[SLEN];    // (y0,y1,y2, 0.5*|y|^2)
    const int tid = threadIdx.x;

    for (int it = blockIdx.x; it < ITEMS; it += G1) {
        const int tx = it & (NTILES - 1);
        const int b  = (it >> 6) & (BATCH - 1);
        const int sp = it >> 9;
        const int tile0 = tx * TILE;
        const int cbase = sp * SLEN;

        const float* xb = xyz  + (size_t)b * NPTS * 3;
        const float* yb = sxyz + ((size_t)b * MPTS + cbase) * 3;

        __syncthreads();   // previous item's sc reads (incl. recompute) done
        for (int j = tid; j < SLEN; j += T1) {
            const float y0 = yb[j * 3 + 0];
            const float y1 = yb[j * 3 + 1];
            const float y2 = yb[j * 3 + 2];
            sc[j] = make_float4(y0, y1, y2, 0.5f * (y0 * y0 + y1 * y1 + y2 * y2));
        }

        float nx[QPT], ny[QPT], nz[QPT], hx[QPT];
        int   k0[QPT], k1[QPT], k2[QPT];
        #pragma unroll
        for (int q = 0; q < QPT; q++) {
            const int n = tile0 + tid + q * T1;
            const float x0 = xb[n * 3 + 0];
            const float x1 = xb[n * 3 + 1];
            const float x2 = xb[n * 3 + 2];
            nx[q] = -x0; ny[q] = -x1; nz[q] = -x2;
            hx[q] = 0.5f * (x0 * x0 + x1 * x1 + x2 * x2);
            k0[q] = 0x7FFFFFFF; k1[q] = 0x7FFFFFFF; k2[q] = 0x7FFFFFFF;
        }
        __syncthreads();

        #pragma unroll 4
        for (int j = 0; j < SLEN; j++) {
            const float4 y = sc[j];          // broadcast LDS.128
            #pragma unroll
            for (int q = 0; q < QPT; q++) {
                // s = 0.5|x|^2 + 0.5|y|^2 - x.y = d/2 >= 0 (mod rounding)
                const float s = fmaf(y.x, nx[q],
                                fmaf(y.y, ny[q],
                                fmaf(y.z, nz[q], hx[q] + y.w)));
                // sortable key: 14 mantissa bits | 9-bit local idx
                const int key = (__float_as_int(s) & (int)0xFFFFFE00) | j;
                // branch-free sorted insert (k0 <= k1 <= k2): 5 IMNMX
                const int M0 = max(k0[q], key);  k0[q] = min(k0[q], key);
                const int M1 = max(k1[q], M0);   k1[q] = min(k1[q], M0);
                k2[q] = min(k2[q], M1);
            }
        }

        // exact-d recompute for the 3 winners + store {d, global_idx}
        #pragma unroll
        for (int q = 0; q < QPT; q++) {
            const int n = tile0 + tid + q * T1;
            const int jj[3] = { k0[q] & (SLEN - 1),
                                k1[q] & (SLEN - 1),
                                k2[q] & (SLEN - 1) };
            #pragma unroll
            for (int r = 0; r < 3; r++) {
                const float4 y = sc[jj[r]];
                const float s = fmaf(y.x, nx[q],
                                fmaf(y.y, ny[q],
                                fmaf(y.z, nz[q], hx[q] + y.w)));
                const float d = 2.0f * s;
                const int slot = sp * 3 + r;
                g_pp[((size_t)b * SPLITS * 3 + slot) * NPTS + n] =
                    make_int2(__float_as_int(d), cbase + jj[r]);
            }
        }
    }
}

// ---------------------------------------------------------------------------
// Phase 2: warp-per-query exact top-3 of 24 partials + interp + concat.
// Grid (2048, 8), 256 threads.
// ---------------------------------------------------------------------------
__device__ __forceinline__ float warp_min_f(float v) {
    #pragma unroll
    for (int off = 16; off > 0; off >>= 1)
        v = fminf(v, __shfl_xor_sync(0xFFFFFFFFu, v, off));
    return v;
}

__global__ __launch_bounds__(256)
void merge_interp_kernel(const float* __restrict__ feat,
                         const float* __restrict__ sfeat,
                         float* __restrict__ out)
{
    const int b    = blockIdx.y;
    const int warp = threadIdx.x >> 5;
    const int lane = threadIdx.x & 31;
    const int n    = blockIdx.x * 8 + warp;

    float dv = CUDART_INF_F;
    int   gi = 0;
    if (lane < SPLITS * 3) {
        const int2 p = g_pp[((size_t)b * SPLITS * 3 + lane) * NPTS + n];
        dv = __int_as_float(p.x);
        gi = p.y;
    }

    // extract top-3: lowest lane on ties == lowest split == lowest global idx
    float dd[3]; int ii[3];
    #pragma unroll
    for (int r = 0; r < 3; r++) {
        const float m = warp_min_f(dv);
        const unsigned ball = __ballot_sync(0xFFFFFFFFu, dv == m);
        const int src = __ffs(ball) - 1;
        dd[r] = m;
        ii[r] = __shfl_sync(0xFFFFFFFFu, gi, src);
        if (lane == src) dv = CUDART_INF_F;
    }

    float d0 = fmaxf(dd[0], 1e-10f);
    float d1 = fmaxf(dd[1], 1e-10f);
    float d2 = fmaxf(dd[2], 1e-10f);
    float w0 = 1.0f / (d0 * d0 + 1e-7f);
    float w1 = 1.0f / (d1 * d1 + 1e-7f);
    float w2 = 1.0f / (d2 * d2 + 1e-7f);
    const float inv = 1.0f / (w0 + w1 + w2 + 1e-10f);
    w0 *= inv; w1 *= inv; w2 *= inv;

    // gather + interpolate + concat
    const float4* sfb = (const float4*)(sfeat + (size_t)b * MPTS * CS);
    const float4* fb  = (const float4*)(feat  + (size_t)b * NPTS * CF);
    float4*       ob  = (float4*)(out + (size_t)b * NPTS * COUT);

    const float4* r0 = sfb + (size_t)ii[0] * (CS / 4);
    const float4* r1 = sfb + (size_t)ii[1] * (CS / 4);
    const float4* r2 = sfb + (size_t)ii[2] * (CS / 4);
    float4* o = ob + (size_t)n * (COUT / 4);

    #pragma unroll
    for (int c = lane; c < CS / 4; c += 32) {
        const float4 a = r0[c];
        const float4 d = r1[c];
        const float4 e = r2[c];
        float4 rv;
        rv.x = w0 * a.x + w1 * d.x + w2 * e.x;
        rv.y = w0 * a.y + w1 * d.y + w2 * e.y;
        rv.z = w0 * a.z + w1 * d.z + w2 * e.z;
        rv.w = w0 * a.w + w1 * d.w + w2 * e.w;
        o[c] = rv;
    }
    const float4* f = fb + (size_t)n * (CF / 4);
    o[CS / 4 + lane] = f[lane];
}

extern "C" void kernel_launch(void* const* d_in, const int* in_sizes, int n_in,
                              void* d_out, int out_size)
{
    const float* xyz   = (const float*)d_in[0];
    const float* sxyz  = (const float*)d_in[1];
    const float* feat  = (const float*)d_in[2];
    const float* sfeat = (const float*)d_in[3];
    float* out = (float*)d_out;

    knn_partial_kernel<<<G1, T1>>>(xyz, sxyz);          // persistent, 1 wave

    dim3 g2(NPTS / 8, BATCH);                           // warp per query
    merge_interp_kernel<<<g2, 256>>>(feat, sfeat, out);
}